// round 17
// baseline (speedup 1.0000x reference)
#include <cuda_runtime.h>
#include <cstdint>

// VoxelBracketPredictor_v2 — 2-kernel pipeline (R16 + wave overlap):
//  k0 bounds: segment boundaries (int4 scan)
//  k1 fused:  CTA = 8 CONTIGUOUS samples, 512 threads, TWO pool warps per sample
//             -> resident pool warps unchanged (32/SM) BUT grid = 512 > 296 slots
//             -> 1.73 waves: wave-2 pooling (DRAM) overlaps wave-1 MLP tails.
//             coarse MLP: CTA-cooperative c-split; refinement: class-sorted
//             warp-per-sample (warps 0..7).

#define EPS 1e-5f
#define BMAX 4096

__device__ int g_bound[BMAX + 1];

// ---------------- kernel 0: boundaries ----------------
__global__ void bounds_kernel(const int* __restrict__ seg, int N, int B) {
    int t = blockIdx.x * blockDim.x + threadIdx.x;
    int i = t * 4;
    if (i >= N) return;
    int vals[4];
    if (i + 4 <= N) {
        int4 v = *(const int4*)(seg + i);
        vals[0] = v.x; vals[1] = v.y; vals[2] = v.z; vals[3] = v.w;
    } else {
        for (int j = 0; j < 4; j++) vals[j] = (i + j < N) ? seg[i + j] : vals[j > 0 ? j - 1 : 0];
    }
    int prev = (i == 0) ? -1 : seg[i - 1];
    int lim = min(4, N - i);
    for (int j = 0; j < lim; j++) {
        int cur = vals[j];
        for (int b = prev + 1; b <= cur; b++) g_bound[b] = i + j;
        prev = cur;
    }
    if (i + 4 >= N)
        for (int b = prev + 1; b <= B; b++) g_bound[b] = N;
}

__device__ __forceinline__ float warpSum(float v) {
#pragma unroll
    for (int o = 16; o; o >>= 1) v += __shfl_xor_sync(0xffffffffu, v, o);
    return v;
}

__device__ __forceinline__ uint32_t smem_u32(const void* p) {
    uint32_t a;
    asm("{ .reg .u64 t; cvta.to.shared.u64 t, %1; cvt.u32.u64 %0, t; }" : "=r"(a) : "l"(p));
    return a;
}
__device__ __forceinline__ void cp_async16(uint32_t saddr, const void* gaddr) {
    asm volatile("cp.async.cg.shared.global [%0], [%1], 16;" :: "r"(saddr), "l"(gaddr));
}
#define CP_COMMIT() asm volatile("cp.async.commit_group;" ::)
#define CP_WAIT(n)  asm volatile("cp.async.wait_group %0;" :: "n"(n))

// dynamic smem layout (floats):
//  [0, 18432)        pool ring: 16 warps x 3 bufs x 384
//    MLP aliases:    actA=[0,2048) (8x256), actB=[2048,3072) (8x128),
//                    part=[3072,7168) (4096)
//  [18432, 19200)    sin_ : 8 x 96
//  [19200, 20736)    spool: 16 x 96 (per-warp pool partials)
#define SMEM_FLOATS 20744

__global__ __launch_bounds__(512, 2) void fused_kernel(
    const float* __restrict__ feat, const int* __restrict__ cls,
    const float* __restrict__ cW1, const float* __restrict__ cb1,
    const float* __restrict__ cg1, const float* __restrict__ cbe1,
    const float* __restrict__ cW2, const float* __restrict__ cb2,
    const float* __restrict__ cg2, const float* __restrict__ cbe2,
    const float* __restrict__ cW3, const float* __restrict__ cb3,
    const float* __restrict__ rW1, const float* __restrict__ rb1,
    const float* __restrict__ rg1, const float* __restrict__ rbe1,
    const float* __restrict__ rW2, const float* __restrict__ rb2,
    const float* __restrict__ rg2, const float* __restrict__ rbe2,
    const float* __restrict__ rW3, const float* __restrict__ rb3,
    float* __restrict__ out, int B)
{
    extern __shared__ float dyns[];
    float* ring = dyns;
    float* actA = dyns;                 // 8 x 256
    float* actB = dyns + 2048;          // 8 x 128
    float* part = dyns + 3072;          // 4096
    float (*sin_)[96]  = reinterpret_cast<float(*)[96]>(dyns + 18432);
    float (*spool)[96] = reinterpret_cast<float(*)[96]>(dyns + 19200);
    float* sinv = dyns + 20736;         // 8
    __shared__ float sstat[8][2];
    __shared__ float scoarse[8][3];
    __shared__ int   scls[8];
    __shared__ int   sslot[8];

    const int tid = threadIdx.x, lane = tid & 31, w = tid >> 5;   // w in [0,16)
    const int b8 = blockIdx.x * 8;

    #define ACTA(s, f) actA[(s) * 256 + (f)]
    #define ACTB(s, f) actB[(s) * 128 + (f)]

    if (tid < 8) scls[tid] = cls[min(b8 + tid, B - 1)];

    // ====== phase 1: cp.async mean pool — TWO warps per sample ======
    {
        const int p = w >> 1, h = w & 1;
        const int bp = min(b8 + p, B - 1);
        const int st = g_bound[bp], en = g_bound[bp + 1];
        const int nrTot = en - st;
        if (h == 0 && lane == 0) sinv[p] = 1.f / fmaxf((float)nrTot, 1.f);
        const int half0 = nrTot >> 1;
        const int rlo = h ? half0 : 0;
        const int nr = h ? (nrTot - half0) : half0;
        const float* gsrc = feat + (size_t)(st + rlo) * 96;
        float* sb = ring + w * 1152;                 // 3 bufs x 384 floats
        const uint32_t sb_u = smem_u32(sb);

        const int T = (nr + 3) >> 2;
        float a0 = 0.f, a1 = 0.f, a2 = 0.f;

        #define ISSUE(i)                                                              \
        {                                                                             \
            const int _i = (i);                                                       \
            const int _cnt = min(4, nr - _i * 4) * 24;                                \
            const uint32_t _sbase = sb_u + (uint32_t)(_i % 3) * 1536u;                \
            const float* _g = gsrc + (size_t)_i * 384;                                \
            if (lane < _cnt)      cp_async16(_sbase + lane * 16u,        _g + lane * 4);        \
            if (lane + 32 < _cnt) cp_async16(_sbase + (lane + 32) * 16u, _g + (lane + 32) * 4); \
            if (lane + 64 < _cnt) cp_async16(_sbase + (lane + 64) * 16u, _g + (lane + 64) * 4); \
            CP_COMMIT();                                                              \
        }

        if (T > 0) ISSUE(0);
        if (T > 1) ISSUE(1);
        if (T > 2) ISSUE(2);

        for (int i = 0; i < T; i++) {
            const int after = T - 1 - i;
            if (after >= 2)      CP_WAIT(2);
            else if (after == 1) CP_WAIT(1);
            else                 CP_WAIT(0);
            __syncwarp();

            const float* bp2 = sb + (i % 3) * 384;
            const int rows = min(4, nr - i * 4);
            if (rows == 4) {
#pragma unroll
                for (int r = 0; r < 4; r++) {
                    a0 += bp2[r * 96 + lane];
                    a1 += bp2[r * 96 + 32 + lane];
                    a2 += bp2[r * 96 + 64 + lane];
                }
            } else {
                for (int r = 0; r < rows; r++) {
                    a0 += bp2[r * 96 + lane];
                    a1 += bp2[r * 96 + 32 + lane];
                    a2 += bp2[r * 96 + 64 + lane];
                }
            }
            __syncwarp();
            if (i + 3 < T) ISSUE(i + 3);
        }
        #undef ISSUE

        spool[w][lane]      = a0;
        spool[w][lane + 32] = a1;
        spool[w][lane + 64] = a2;
    }
    // class sort (8 samples), while other warps finish pooling
    if (tid == 0) {
        int cnt[4] = {0, 0, 0, 0};
        for (int s = 0; s < 8; s++) cnt[scls[s]]++;
        int base[4];
        base[0] = 0;
        for (int kk = 1; kk < 4; kk++) base[kk] = base[kk - 1] + cnt[kk - 1];
        for (int s = 0; s < 8; s++) sslot[base[scls[s]]++] = s;
    }
    __syncthreads();

    // combine the two half-sums -> sin_
    for (int idx = tid; idx < 8 * 96; idx += 512) {
        int p = idx / 96, c = idx - 96 * p;
        sin_[p][c] = (spool[2 * p][c] + spool[2 * p + 1][c]) * sinv[p];
    }
    __syncthreads();

    // ================= coarse L1 (96 -> 256), c-split (2 halves) ============
    const int f1 = tid & 255, h1 = tid >> 8;
    {
        float acc[8];
        const float bv = (h1 == 0) ? cb1[f1] : 0.f;
#pragma unroll
        for (int s = 0; s < 8; s++) acc[s] = bv;
        const int c0 = h1 * 48;
#pragma unroll 2
        for (int cc = 0; cc < 48; cc += 4) {
            const int c = c0 + cc;
            float w0 = cW1[(c + 0) * 256 + f1];
            float w1 = cW1[(c + 1) * 256 + f1];
            float w2 = cW1[(c + 2) * 256 + f1];
            float w3 = cW1[(c + 3) * 256 + f1];
#pragma unroll
            for (int s = 0; s < 8; s++) {
                float4 x = *(const float4*)(&sin_[s][c]);
                acc[s] = fmaf(x.x, w0, acc[s]);
                acc[s] = fmaf(x.y, w1, acc[s]);
                acc[s] = fmaf(x.z, w2, acc[s]);
                acc[s] = fmaf(x.w, w3, acc[s]);
            }
        }
#pragma unroll
        for (int s = 0; s < 8; s++) part[h1 * 2048 + s * 256 + f1] = acc[s];
    }
    __syncthreads();
    if (w < 8) {   // LN stats over 256 (warp w -> sample w)
        float sum = 0.f, sq = 0.f;
#pragma unroll
        for (int j = 0; j < 8; j++) {
            int f = lane + 32 * j;
            float x = part[w * 256 + f] + part[2048 + w * 256 + f];
            sum += x; sq = fmaf(x, x, sq);
        }
        sum = warpSum(sum); sq = warpSum(sq);
        if (lane == 0) {
            float m = sum * (1.f / 256.f);
            float v = sq * (1.f / 256.f) - m * m;
            sstat[w][0] = m; sstat[w][1] = rsqrtf(v + EPS);
        }
    }
    __syncthreads();
    {   // combine + LN + ReLU -> ACTA ; thread covers samples s = h1 + 2i
        const float g = cg1[f1], e = cbe1[f1];
#pragma unroll
        for (int i = 0; i < 4; i++) {
            const int s = h1 + 2 * i;
            float x = part[s * 256 + f1] + part[2048 + s * 256 + f1];
            ACTA(s, f1) = fmaxf(fmaf((x - sstat[s][0]) * sstat[s][1], g, e), 0.f);
        }
    }
    __syncthreads();

    // ================= coarse L2 (256 -> 128), c-split (4 quarters) =========
    const int f2q = tid & 127, q2 = tid >> 7;
    {
        float acc[8];
        const float bv = (q2 == 0) ? cb2[f2q] : 0.f;
#pragma unroll
        for (int s = 0; s < 8; s++) acc[s] = bv;
        const int c0 = q2 * 64;
#pragma unroll 2
        for (int cc = 0; cc < 64; cc += 4) {
            const int c = c0 + cc;
            float w0 = cW2[(c + 0) * 128 + f2q];
            float w1 = cW2[(c + 1) * 128 + f2q];
            float w2 = cW2[(c + 2) * 128 + f2q];
            float w3 = cW2[(c + 3) * 128 + f2q];
#pragma unroll
            for (int s = 0; s < 8; s++) {
                float4 x = *(const float4*)(&ACTA(s, c));
                acc[s] = fmaf(x.x, w0, acc[s]);
                acc[s] = fmaf(x.y, w1, acc[s]);
                acc[s] = fmaf(x.z, w2, acc[s]);
                acc[s] = fmaf(x.w, w3, acc[s]);
            }
        }
#pragma unroll
        for (int s = 0; s < 8; s++) part[q2 * 1024 + s * 128 + f2q] = acc[s];
    }
    __syncthreads();
    if (w < 8) {   // LN stats over 128
        float sum = 0.f, sq = 0.f;
#pragma unroll
        for (int j = 0; j < 4; j++) {
            int f = lane + 32 * j;
            float x = part[w * 128 + f] + part[1024 + w * 128 + f]
                    + part[2048 + w * 128 + f] + part[3072 + w * 128 + f];
            sum += x; sq = fmaf(x, x, sq);
        }
        sum = warpSum(sum); sq = warpSum(sq);
        if (lane == 0) {
            float m = sum * (1.f / 128.f);
            float v = sq * (1.f / 128.f) - m * m;
            sstat[w][0] = m; sstat[w][1] = rsqrtf(v + EPS);
        }
    }
    __syncthreads();
    {   // combine + LN + ReLU -> ACTB ; thread covers samples s = q2 + 4i
        const float g = cg2[f2q], e = cbe2[f2q];
#pragma unroll
        for (int i = 0; i < 2; i++) {
            const int s = q2 + 4 * i;
            float x = part[s * 128 + f2q] + part[1024 + s * 128 + f2q]
                    + part[2048 + s * 128 + f2q] + part[3072 + s * 128 + f2q];
            ACTB(s, f2q) = fmaxf(fmaf((x - sstat[s][0]) * sstat[s][1], g, e), 0.f);
        }
    }
    __syncthreads();

    // ================= coarse L3 (warps 0..7 -> sample w) -> scoarse ========
    if (w < 8) {
        float p0 = 0.f, p1 = 0.f, p2 = 0.f;
#pragma unroll
        for (int t = 0; t < 4; t++) {
            int c = lane + 32 * t;
            float x = ACTB(w, c);
            p0 = fmaf(x, cW3[c * 3 + 0], p0);
            p1 = fmaf(x, cW3[c * 3 + 1], p1);
            p2 = fmaf(x, cW3[c * 3 + 2], p2);
        }
        p0 = warpSum(p0) + cb3[0];
        p1 = warpSum(p1) + cb3[1];
        p2 = warpSum(p2) + cb3[2];
        if (lane < 3)
            scoarse[w][lane] = (lane == 0) ? p0 : (lane == 1) ? p1 : p2;
    }
    __syncthreads();

    // ================= refinement: warps 0..7, class-sorted samples =========
    if (w < 8) {
        const int s = sslot[w];
        const int k = scls[s];
        const int f4 = lane * 4, f2 = lane * 2;

        // refine L1: 96 -> 128
        {
            const float* W = rW1 + k * 96 * 128;
            float4 bb = *(const float4*)(rb1 + k * 128 + f4);
            float B0[4] = {bb.x, bb.y, bb.z, bb.w};
#pragma unroll 2
            for (int c = 0; c < 96; c += 4) {
                float4 x = *(const float4*)(&sin_[s][c]);
                float4 wv;
                wv = *(const float4*)(W + (c + 0) * 128 + f4);
                B0[0] = fmaf(x.x, wv.x, B0[0]); B0[1] = fmaf(x.x, wv.y, B0[1]);
                B0[2] = fmaf(x.x, wv.z, B0[2]); B0[3] = fmaf(x.x, wv.w, B0[3]);
                wv = *(const float4*)(W + (c + 1) * 128 + f4);
                B0[0] = fmaf(x.y, wv.x, B0[0]); B0[1] = fmaf(x.y, wv.y, B0[1]);
                B0[2] = fmaf(x.y, wv.z, B0[2]); B0[3] = fmaf(x.y, wv.w, B0[3]);
                wv = *(const float4*)(W + (c + 2) * 128 + f4);
                B0[0] = fmaf(x.z, wv.x, B0[0]); B0[1] = fmaf(x.z, wv.y, B0[1]);
                B0[2] = fmaf(x.z, wv.z, B0[2]); B0[3] = fmaf(x.z, wv.w, B0[3]);
                wv = *(const float4*)(W + (c + 3) * 128 + f4);
                B0[0] = fmaf(x.w, wv.x, B0[0]); B0[1] = fmaf(x.w, wv.y, B0[1]);
                B0[2] = fmaf(x.w, wv.z, B0[2]); B0[3] = fmaf(x.w, wv.w, B0[3]);
            }
            float m = warpSum(B0[0] + B0[1] + B0[2] + B0[3]) * (1.f / 128.f);
            float v = 0.f;
#pragma unroll
            for (int j = 0; j < 4; j++) { float d = B0[j] - m; v = fmaf(d, d, v); }
            float r = rsqrtf(warpSum(v) * (1.f / 128.f) + EPS);
            float4 g = *(const float4*)(rg1 + k * 128 + f4);
            float4 e = *(const float4*)(rbe1 + k * 128 + f4);
            float4 o;
            o.x = fmaxf(fmaf((B0[0] - m) * r, g.x, e.x), 0.f);
            o.y = fmaxf(fmaf((B0[1] - m) * r, g.y, e.y), 0.f);
            o.z = fmaxf(fmaf((B0[2] - m) * r, g.z, e.z), 0.f);
            o.w = fmaxf(fmaf((B0[3] - m) * r, g.w, e.w), 0.f);
            *(float4*)(&ACTA(s, f4)) = o;
        }
        __syncwarp();

        // refine L2: 128 -> 64
        float r2out0, r2out1;
        {
            const float* W = rW2 + k * 128 * 64;
            float2 bb = *(const float2*)(rb2 + k * 64 + f2);
            float D0[2] = {bb.x, bb.y};
#pragma unroll 2
            for (int c = 0; c < 128; c += 4) {
                float4 x = *(const float4*)(&ACTA(s, c));
                float2 wv;
                wv = *(const float2*)(W + (c + 0) * 64 + f2);
                D0[0] = fmaf(x.x, wv.x, D0[0]); D0[1] = fmaf(x.x, wv.y, D0[1]);
                wv = *(const float2*)(W + (c + 1) * 64 + f2);
                D0[0] = fmaf(x.y, wv.x, D0[0]); D0[1] = fmaf(x.y, wv.y, D0[1]);
                wv = *(const float2*)(W + (c + 2) * 64 + f2);
                D0[0] = fmaf(x.z, wv.x, D0[0]); D0[1] = fmaf(x.z, wv.y, D0[1]);
                wv = *(const float2*)(W + (c + 3) * 64 + f2);
                D0[0] = fmaf(x.w, wv.x, D0[0]); D0[1] = fmaf(x.w, wv.y, D0[1]);
            }
            float m = warpSum(D0[0] + D0[1]) * (1.f / 64.f);
            float d0 = D0[0] - m, d1 = D0[1] - m;
            float r = rsqrtf(warpSum(d0 * d0 + d1 * d1) * (1.f / 64.f) + EPS);
            float2 g = *(const float2*)(rg2 + k * 64 + f2);
            float2 e = *(const float2*)(rbe2 + k * 64 + f2);
            r2out0 = fmaxf(fmaf(d0 * r, g.x, e.x), 0.f);
            r2out1 = fmaxf(fmaf(d1 * r, g.y, e.y), 0.f);
        }
        __syncwarp();

        // refine L3: 64 -> 3 via shuffles, add coarse(s), write out sample s
        {
            const float* W3 = rW3 + k * 192;
            float q0 = r2out0 * W3[f2 * 3 + 0] + r2out1 * W3[(f2 + 1) * 3 + 0];
            float q1 = r2out0 * W3[f2 * 3 + 1] + r2out1 * W3[(f2 + 1) * 3 + 1];
            float q2 = r2out0 * W3[f2 * 3 + 2] + r2out1 * W3[(f2 + 1) * 3 + 2];
            q0 = warpSum(q0) + rb3[k * 3 + 0];
            q1 = warpSum(q1) + rb3[k * 3 + 1];
            q2 = warpSum(q2) + rb3[k * 3 + 2];

            if ((b8 + s) < B && lane < 3) {
                float qc = (lane == 0) ? q0 : (lane == 1) ? q1 : q2;
                out[(b8 + s) * 3 + lane] = scoarse[s][lane] + qc;
            }
        }
    }
    #undef ACTA
    #undef ACTB
}

// ---------------- launch ----------------
extern "C" void kernel_launch(void* const* d_in, const int* in_sizes, int n_in,
                              void* d_out, int out_size) {
    const float* feat = (const float*)d_in[0];
    const int*   seg  = (const int*)d_in[1];
    const int*   cls  = (const int*)d_in[2];
    const int N = in_sizes[1];
    const int B = in_sizes[2];

    const int smem_bytes = SMEM_FLOATS * 4;       // ~83 KB -> 2 CTAs/SM, grid 512 -> 1.73 waves
    cudaFuncSetAttribute(fused_kernel, cudaFuncAttributeMaxDynamicSharedMemorySize,
                         smem_bytes);

    bounds_kernel<<<(N / 4 + 255) / 256, 256>>>(seg, N, B);
    fused_kernel<<<(B + 7) / 8, 512, smem_bytes>>>(
        feat, cls,
        (const float*)d_in[3],  (const float*)d_in[4],  (const float*)d_in[5],  (const float*)d_in[6],
        (const float*)d_in[7],  (const float*)d_in[8],  (const float*)d_in[9],  (const float*)d_in[10],
        (const float*)d_in[11], (const float*)d_in[12],
        (const float*)d_in[13], (const float*)d_in[14], (const float*)d_in[15], (const float*)d_in[16],
        (const float*)d_in[17], (const float*)d_in[18], (const float*)d_in[19], (const float*)d_in[20],
        (const float*)d_in[21], (const float*)d_in[22],
        (float*)d_out, B);
}